// round 12
// baseline (speedup 1.0000x reference)
#include <cuda_runtime.h>
#include <cuda_bf16.h>

#define NN 50000
#define EE 800000
#define DD 128
#define NBLK 196          // ceil(50000/256) scan chunks
#define GRIDG 782         // ceil(50000/64) gemm tiles
#define NCSR 256          // CSR-builder blocks inside k_mega (must be <= wave-1 residency)

typedef unsigned long long u64;

// ---------------- scratch (no allocations allowed) ----------------
// NEVER passed from host as kernel args (host-side symbol = ATS host memory!).
// Every kernel touching these references them directly in device code.
__device__ int   g_dege[NN];        // edge-only in-degree
__device__ float g_dinv[NN];        // rsqrt(deg_e + 1)
__device__ int   g_rows[NN];        // CSR row start
__device__ int   g_cursor[NN];      // fill cursors
__device__ int   g_part[256];       // scan block partials
__device__ int   g_csrc[EE];        // CSR: source node per slot
__device__ float g_bufA[NN * DD];   // pre-scaled gemm output Hs = (XW)*dinv
__device__ float g_bufB[NN * DD];   // layer-1 activations (gemm2 input)
__device__ int   g_bar[4];          // software barrier counters (CSR blocks)
__device__ int   g_flag;            // dinv-ready flag

// ================= reset (per call; graph-replay safe) =================
__global__ void k_reset() {
    if (threadIdx.x < 4) g_bar[threadIdx.x] = 0;
    if (threadIdx.x == 4) g_flag = 0;
}

// barrier among the NCSR CSR blocks only
__device__ __forceinline__ void csr_barrier(int p) {
    __syncthreads();
    if (threadIdx.x == 0) {
        __threadfence();
        atomicAdd(&g_bar[p], 1);
        while (*(volatile int*)&g_bar[p] < NCSR) __nanosleep(32);
        __threadfence();
    }
    __syncthreads();
}

// ================= GEMM core: Hs[64,128] = (X @ W) * dinv ====================
// 8 rows x 4 cols per thread as 4 row-pair f32x2 accumulators x 4 cols.
// Per k: 1x LDS.128 (w) + 4x LDS.64 (x pairs, uniform) + 4 dup + 16 fma.rn.f32x2.
__device__ __forceinline__ void gemm_core(int bid, const float* __restrict__ X,
                                          const float* __restrict__ W,
                                          float* __restrict__ Y, int M,
                                          float* sW, float* sX, int waitflag) {
    int tid  = threadIdx.x;
    int row0 = bid * 64;
    int nrows = M - row0; if (nrows > 64) nrows = 64;

    int tc = tid & 31;
    int tr = tid >> 5;

    u64 acc2[4][4];
#pragma unroll
    for (int rp = 0; rp < 4; rp++)
#pragma unroll
        for (int c = 0; c < 4; c++) acc2[rp][c] = 0ULL;

    const float4* W4 = (const float4*)W;
    const float4* X4 = (const float4*)X;

    for (int kk = 0; kk < 128; kk += 64) {
        for (int i = tid; i < 64 * 32; i += 256) {
            int k  = i >> 5;
            int c4 = i & 31;
            ((float4*)sW)[i] = W4[(kk + k) * 32 + c4];
        }
        for (int i = tid; i < 64 * 16; i += 256) {
            int c4 = i >> 6;
            int r  = i & 63;
            float4 v = make_float4(0.f, 0.f, 0.f, 0.f);
            if (r < nrows) v = X4[(size_t)(row0 + r) * 32 + (kk >> 2) + c4];
            int kb = c4 * 4;
            sX[(kb + 0) * 64 + r] = v.x;
            sX[(kb + 1) * 64 + r] = v.y;
            sX[(kb + 2) * 64 + r] = v.z;
            sX[(kb + 3) * 64 + r] = v.w;
        }
        __syncthreads();

        const float4* sW4 = (const float4*)sW;
        const u64*    sX2 = (const u64*)sX;
#pragma unroll
        for (int k = 0; k < 64; k++) {
            float4 w = sW4[k * 32 + tc];
            u64 wd[4];
            asm("mov.b64 %0, {%1, %1};" : "=l"(wd[0]) : "r"(__float_as_uint(w.x)));
            asm("mov.b64 %0, {%1, %1};" : "=l"(wd[1]) : "r"(__float_as_uint(w.y)));
            asm("mov.b64 %0, {%1, %1};" : "=l"(wd[2]) : "r"(__float_as_uint(w.z)));
            asm("mov.b64 %0, {%1, %1};" : "=l"(wd[3]) : "r"(__float_as_uint(w.w)));
            u64 xp[4];
            xp[0] = sX2[k * 32 + tr * 4 + 0];
            xp[1] = sX2[k * 32 + tr * 4 + 1];
            xp[2] = sX2[k * 32 + tr * 4 + 2];
            xp[3] = sX2[k * 32 + tr * 4 + 3];
#pragma unroll
            for (int rp = 0; rp < 4; rp++) {
#pragma unroll
                for (int c = 0; c < 4; c++) {
                    asm("fma.rn.f32x2 %0, %1, %2, %0;"
                        : "+l"(acc2[rp][c]) : "l"(xp[rp]), "l"(wd[c]));
                }
            }
        }
        __syncthreads();
    }

    if (waitflag) {   // dinv must be ready before the scaled epilogue
        if (tid == 0) {
            while (*(volatile int*)&g_flag == 0) __nanosleep(32);
        }
        __syncthreads();
        __threadfence();
    }

#pragma unroll
    for (int rp = 0; rp < 4; rp++) {
        unsigned lo[4], hi[4];
#pragma unroll
        for (int c = 0; c < 4; c++)
            asm("mov.b64 {%0, %1}, %2;" : "=r"(lo[c]), "=r"(hi[c]) : "l"(acc2[rp][c]));
        int rowe = row0 + tr * 8 + rp * 2;
        if (rowe < M) {
            float d = g_dinv[rowe];
            float4 v = make_float4(__uint_as_float(lo[0]) * d, __uint_as_float(lo[1]) * d,
                                   __uint_as_float(lo[2]) * d, __uint_as_float(lo[3]) * d);
            ((float4*)(Y + (size_t)rowe * DD))[tc] = v;
        }
        if (rowe + 1 < M) {
            float d = g_dinv[rowe + 1];
            float4 v = make_float4(__uint_as_float(hi[0]) * d, __uint_as_float(hi[1]) * d,
                                   __uint_as_float(hi[2]) * d, __uint_as_float(hi[3]) * d);
            ((float4*)(Y + (size_t)(rowe + 1) * DD))[tc] = v;
        }
    }
}

// ================= mega kernel: CSR build (blocks 0..NCSR) || gemm1 ==========
__global__ void __launch_bounds__(256) k_mega(const int* __restrict__ src,
                                              const int* __restrict__ dst,
                                              const float* __restrict__ X,
                                              const float* __restrict__ W) {
    __shared__ float pool[64 * 128 + 64 * 64];   // 48KB, reused by both roles

    if (blockIdx.x >= NCSR) {
        gemm_core(blockIdx.x - NCSR, X, W, g_bufA, NN, pool, pool + 64 * 128, 1);
        return;
    }

    int bid = blockIdx.x;
    int tid = threadIdx.x;
    int gthr = bid * 256 + tid;
    int* s = (int*)pool;

    // phase 0: zero degrees
    for (int i = gthr; i < NN; i += NCSR * 256) g_dege[i] = 0;
    csr_barrier(0);

    // phase 1: count in-degrees
    for (int e = gthr; e < EE; e += NCSR * 256) atomicAdd(&g_dege[dst[e]], 1);
    csr_barrier(1);

    // phase 2: per-chunk exclusive scan (chunks 0..NBLK)
    if (bid < NBLK) {
        int i = bid * 256 + tid;
        int v = (i < NN) ? g_dege[i] : 0;
        s[tid] = v;
        __syncthreads();
#pragma unroll
        for (int off = 1; off < 256; off <<= 1) {
            int t = (tid >= off) ? s[tid - off] : 0;
            __syncthreads();
            s[tid] += t;
            __syncthreads();
        }
        if (i < NN) g_rows[i] = s[tid] - v;
        if (tid == 255) g_part[bid] = s[255];
    }
    csr_barrier(2);

    // phase 3: apply chunk offsets, write cursors + dinv
    if (bid < NBLK) {
        s[tid] = (tid < bid) ? g_part[tid] : 0;
        __syncthreads();
#pragma unroll
        for (int off = 128; off > 0; off >>= 1) {
            if (tid < off) s[tid] += s[tid + off];
            __syncthreads();
        }
        int offset = s[0];
        int i = bid * 256 + tid;
        if (i < NN) {
            int rs = g_rows[i] + offset;
            g_rows[i]   = rs;
            g_cursor[i] = rs;
            g_dinv[i]   = rsqrtf((float)(g_dege[i] + 1));
        }
    }
    csr_barrier(3);

    // signal gemm epilogues: dinv is ready
    if (bid == 0 && tid == 0) {
        __threadfence();
        *(volatile int*)&g_flag = 1;
    }

    // phase 4: CSR fill
    for (int e = gthr; e < EE; e += NCSR * 256) {
        int d = dst[e];
        int pos = atomicAdd(&g_cursor[d], 1);
        g_csrc[pos] = src[e];
    }
}

__global__ void __launch_bounds__(256) k_gemm2(const float* __restrict__ W) {
    __shared__ float pool[64 * 128 + 64 * 64];
    gemm_core(blockIdx.x, g_bufB, W, g_bufA, NN, pool, pool + 64 * 128, 0);
}

// ================= aggregation: warp per node, ILP-4 gathers, no atomics ======
// bufA holds Hs = (XW)*dinv.  res = dinv[i] * ( Hs[i] + sum_{s->i} Hs[s] )
__device__ __forceinline__ float4 agg_node(int i, int lane) {
    const float4* H4 = (const float4*)g_bufA;
    float di = g_dinv[i];

    float4 acc = H4[(size_t)i * 32 + lane];   // self term (pre-scaled)
    int j  = g_rows[i];
    int en = j + g_dege[i];
    for (; j + 4 <= en; j += 4) {
        int s0 = __ldg(&g_csrc[j]);
        int s1 = __ldg(&g_csrc[j + 1]);
        int s2 = __ldg(&g_csrc[j + 2]);
        int s3 = __ldg(&g_csrc[j + 3]);
        float4 v0 = H4[(size_t)s0 * 32 + lane];
        float4 v1 = H4[(size_t)s1 * 32 + lane];
        float4 v2 = H4[(size_t)s2 * 32 + lane];
        float4 v3 = H4[(size_t)s3 * 32 + lane];
        acc.x += v0.x + v1.x + v2.x + v3.x;
        acc.y += v0.y + v1.y + v2.y + v3.y;
        acc.z += v0.z + v1.z + v2.z + v3.z;
        acc.w += v0.w + v1.w + v2.w + v3.w;
    }
    for (; j < en; j++) {
        int s = __ldg(&g_csrc[j]);
        float4 v = H4[(size_t)s * 32 + lane];
        acc.x += v.x; acc.y += v.y; acc.z += v.z; acc.w += v.w;
    }
    acc.x *= di; acc.y *= di; acc.z *= di; acc.w *= di;
    return acc;
}

// layer-1 epilogue: relu(acc + b1) -> g_bufB
__global__ void k_agg_relu(const float* __restrict__ b) {
    int gid  = blockIdx.x * blockDim.x + threadIdx.x;
    int i    = gid >> 5;
    if (i >= NN) return;
    int lane = gid & 31;

    float4 acc = agg_node(i, lane);
    float4 bb = ((const float4*)b)[lane];
    acc.x = fmaxf(acc.x + bb.x, 0.f);
    acc.y = fmaxf(acc.y + bb.y, 0.f);
    acc.z = fmaxf(acc.z + bb.z, 0.f);
    acc.w = fmaxf(acc.w + bb.w, 0.f);
    ((float4*)(g_bufB + (size_t)i * DD))[lane] = acc;
}

// layer-2 epilogue: relu(acc + b2), then two head dot-products -> out
__global__ void k_agg_heads(const float* __restrict__ b2,
                            const float* __restrict__ Wt, const float* __restrict__ bt,
                            const float* __restrict__ We, const float* __restrict__ be,
                            float* __restrict__ out) {
    int gid  = blockIdx.x * blockDim.x + threadIdx.x;
    int i    = gid >> 5;
    if (i >= NN) return;
    int lane = gid & 31;

    float4 acc = agg_node(i, lane);
    float4 bb = ((const float4*)b2)[lane];
    acc.x = fmaxf(acc.x + bb.x, 0.f);
    acc.y = fmaxf(acc.y + bb.y, 0.f);
    acc.z = fmaxf(acc.z + bb.z, 0.f);
    acc.w = fmaxf(acc.w + bb.w, 0.f);

    float4 wt = ((const float4*)Wt)[lane];
    float4 we = ((const float4*)We)[lane];
    float stv = acc.x * wt.x + acc.y * wt.y + acc.z * wt.z + acc.w * wt.w;
    float evv = acc.x * we.x + acc.y * we.y + acc.z * we.z + acc.w * we.w;
#pragma unroll
    for (int off = 16; off > 0; off >>= 1) {
        stv += __shfl_xor_sync(0xFFFFFFFF, stv, off);
        evv += __shfl_xor_sync(0xFFFFFFFF, evv, off);
    }
    if (lane == 0) {
        out[i]      = stv + bt[0];
        out[NN + i] = evv + be[0];
    }
}

// ================= launch =================
extern "C" void kernel_launch(void* const* d_in, const int* in_sizes, int n_in,
                              void* d_out, int out_size) {
    const float* x  = (const float*)d_in[0];
    const int*   ei = (const int*)  d_in[1];
    const float* W1 = (const float*)d_in[2];
    const float* b1 = (const float*)d_in[3];
    const float* W2 = (const float*)d_in[4];
    const float* b2 = (const float*)d_in[5];
    const float* Wt = (const float*)d_in[6];
    const float* bt = (const float*)d_in[7];
    const float* We = (const float*)d_in[8];
    const float* be = (const float*)d_in[9];
    float* out = (float*)d_out;

    const int* src = ei;        // edge_index[0]
    const int* dst = ei + EE;   // edge_index[1]

    const int T = 256;
    int gridN32 = (NN * 32 + T - 1) / T; // 6250

    k_reset    <<<1, 32>>>();
    k_mega     <<<NCSR + GRIDG, T>>>(src, dst, x, W1);   // CSR build || gemm1
    k_agg_relu <<<gridN32, T>>>(b1);
    k_gemm2    <<<GRIDG, T>>>(W2);
    k_agg_heads<<<gridN32, T>>>(b2, Wt, bt, We, be, out);
}

// round 17
// speedup vs baseline: 1.2946x; 1.2946x over previous
#include <cuda_runtime.h>
#include <cuda_bf16.h>

#define NN 50000
#define EE 800000
#define DD 128
#define NBLK 196          // ceil(50000/256) scan chunks
#define GRIDG 782         // ceil(50000/64) gemm tiles
#define GRIDE 3125        // ceil(800000/256) fill blocks

// padded smem strides (conflict-free MMA fragment loads)
#define SXS 36            // sX row stride (64 rows x 32 k)
#define SWS 132           // sW row stride (32 k x 128 n)

typedef unsigned long long u64;

// ---------------- scratch (no allocations allowed) ----------------
// NEVER passed from host as kernel args (host-side symbol = ATS host memory!).
// Every kernel touching these references them directly in device code.
__device__ int   g_dege[NN];        // edge-only in-degree
__device__ float g_dinv[NN];        // rsqrt(deg_e + 1)
__device__ int   g_rows[NN];        // CSR row start
__device__ int   g_cursor[NN];      // fill cursors
__device__ int   g_part[256];       // scan block partials
__device__ int   g_csrc[EE];        // CSR: source node per slot
__device__ float g_bufA[NN * DD];   // pre-scaled gemm output Hs = (XW)*dinv
__device__ float g_bufB[NN * DD];   // layer-1 activations (gemm2 input)

// ================= CSR build =================
__global__ void k_zero() {
    int i = blockIdx.x * blockDim.x + threadIdx.x;
    if (i < NN) g_dege[i] = 0;
}

__global__ void k_count(const int* __restrict__ dst) {
    int e = blockIdx.x * blockDim.x + threadIdx.x;
    if (e < EE) atomicAdd(&g_dege[dst[e]], 1);
}

__global__ void k_scanA() {
    __shared__ int s[256];
    int tid = threadIdx.x;
    int i = blockIdx.x * 256 + tid;
    int v = (i < NN) ? g_dege[i] : 0;
    s[tid] = v;
    __syncthreads();
#pragma unroll
    for (int off = 1; off < 256; off <<= 1) {
        int t = (tid >= off) ? s[tid - off] : 0;
        __syncthreads();
        s[tid] += t;
        __syncthreads();
    }
    if (i < NN) g_rows[i] = s[tid] - v;   // local exclusive
    if (tid == 255) g_part[blockIdx.x] = s[255];
}

// finalize: each block reduces its prefix of the 196 partials, applies offset,
// writes cursors and dinv.
__global__ void k_scanC() {
    __shared__ int s[256];
    int tid = threadIdx.x;
    s[tid] = (tid < (int)blockIdx.x && tid < NBLK) ? g_part[tid] : 0;
    __syncthreads();
#pragma unroll
    for (int off = 128; off > 0; off >>= 1) {
        if (tid < off) s[tid] += s[tid + off];
        __syncthreads();
    }
    int offset = s[0];
    int i = blockIdx.x * 256 + tid;
    if (i >= NN) return;
    int rs = g_rows[i] + offset;
    g_rows[i]   = rs;
    g_cursor[i] = rs;
    g_dinv[i]   = rsqrtf((float)(g_dege[i] + 1));
}

// ================= tf32 tensor-core GEMM =====================================
// Hs[64,128] = (X @ W) * dinv.  Block = 256 threads = 8 warps (2 m x 4 n).
// Warp tile 32x32 = 2 m16 x 4 n8 tiles of mma.m16n8k8.tf32, fp32 accumulate.
// K processed in 4 chunks of 32; operands cvt.rna'd to tf32 at smem store.
__device__ __forceinline__ unsigned f2tf32(float f) {
    unsigned r;
    asm("cvt.rna.tf32.f32 %0, %1;" : "=r"(r) : "f"(f));
    return r;
}

__device__ __forceinline__ void gemm_core(int bid, const float* __restrict__ X,
                                          const float* __restrict__ W,
                                          float* __restrict__ Y, int M,
                                          float* sX, float* sW) {
    int tid  = threadIdx.x;
    int row0 = bid * 64;
    int nrows = M - row0; if (nrows > 64) nrows = 64;

    int lane = tid & 31;
    int w    = tid >> 5;
    int wm   = w & 1;        // m half: rows [wm*32, +32)
    int wn   = w >> 1;       // n quarter: cols [wn*32, +32)
    int qr   = lane >> 2;    // 0..7
    int qk   = lane & 3;     // 0..3

    float acc[2][4][4];
#pragma unroll
    for (int mi = 0; mi < 2; mi++)
#pragma unroll
        for (int ni = 0; ni < 4; ni++)
#pragma unroll
            for (int c = 0; c < 4; c++) acc[mi][ni][c] = 0.f;

    const float4* X4 = (const float4*)X;
    const float4* W4 = (const float4*)W;

    for (int kk = 0; kk < 128; kk += 32) {
        // load X[row0..+64][kk..+32) -> sX[r][k], tf32-rounded. 512 float4s.
#pragma unroll
        for (int j = 0; j < 2; j++) {
            int idx = tid + 256 * j;
            int r  = idx >> 3;
            int c4 = idx & 7;
            float4 v = make_float4(0.f, 0.f, 0.f, 0.f);
            if (r < nrows) v = X4[(size_t)(row0 + r) * 32 + (kk >> 2) + c4];
            float* p = sX + r * SXS + c4 * 4;
            p[0] = __uint_as_float(f2tf32(v.x));
            p[1] = __uint_as_float(f2tf32(v.y));
            p[2] = __uint_as_float(f2tf32(v.z));
            p[3] = __uint_as_float(f2tf32(v.w));
        }
        // load W[kk..+32)[0..128) -> sW[k][n], tf32-rounded. 1024 float4s.
#pragma unroll
        for (int j = 0; j < 4; j++) {
            int idx = tid + 256 * j;
            int k  = idx >> 5;
            int c4 = idx & 31;
            float4 v = W4[(size_t)(kk + k) * 32 + c4];
            float* p = sW + k * SWS + c4 * 4;
            p[0] = __uint_as_float(f2tf32(v.x));
            p[1] = __uint_as_float(f2tf32(v.y));
            p[2] = __uint_as_float(f2tf32(v.z));
            p[3] = __uint_as_float(f2tf32(v.w));
        }
        __syncthreads();

#pragma unroll
        for (int ks = 0; ks < 4; ks++) {
            int k8 = ks * 8;
            unsigned a[2][4], b[4][2];
#pragma unroll
            for (int mi = 0; mi < 2; mi++) {
                int r = wm * 32 + mi * 16 + qr;
                a[mi][0] = __float_as_uint(sX[r * SXS + k8 + qk]);
                a[mi][1] = __float_as_uint(sX[(r + 8) * SXS + k8 + qk]);
                a[mi][2] = __float_as_uint(sX[r * SXS + k8 + qk + 4]);
                a[mi][3] = __float_as_uint(sX[(r + 8) * SXS + k8 + qk + 4]);
            }
#pragma unroll
            for (int ni = 0; ni < 4; ni++) {
                int n = wn * 32 + ni * 8 + qr;
                b[ni][0] = __float_as_uint(sW[(k8 + qk) * SWS + n]);
                b[ni][1] = __float_as_uint(sW[(k8 + qk + 4) * SWS + n]);
            }
#pragma unroll
            for (int mi = 0; mi < 2; mi++)
#pragma unroll
                for (int ni = 0; ni < 4; ni++) {
                    asm("mma.sync.aligned.m16n8k8.row.col.f32.tf32.tf32.f32 "
                        "{%0,%1,%2,%3}, {%4,%5,%6,%7}, {%8,%9}, {%0,%1,%2,%3};"
                        : "+f"(acc[mi][ni][0]), "+f"(acc[mi][ni][1]),
                          "+f"(acc[mi][ni][2]), "+f"(acc[mi][ni][3])
                        : "r"(a[mi][0]), "r"(a[mi][1]), "r"(a[mi][2]), "r"(a[mi][3]),
                          "r"(b[ni][0]), "r"(b[ni][1]));
                }
        }
        __syncthreads();
    }

    // epilogue: scale rows by dinv, store float2 (c0,c1)/(c2,c3) pairs
#pragma unroll
    for (int mi = 0; mi < 2; mi++) {
        int ra = row0 + wm * 32 + mi * 16 + qr;
        int rb = ra + 8;
        float da = (ra < M) ? g_dinv[ra] : 0.f;
        float db = (rb < M) ? g_dinv[rb] : 0.f;
#pragma unroll
        for (int ni = 0; ni < 4; ni++) {
            int col = wn * 32 + ni * 8 + 2 * qk;
            if (ra < M) {
                float2 v = make_float2(acc[mi][ni][0] * da, acc[mi][ni][1] * da);
                *(float2*)(Y + (size_t)ra * DD + col) = v;
            }
            if (rb < M) {
                float2 v = make_float2(acc[mi][ni][2] * db, acc[mi][ni][3] * db);
                *(float2*)(Y + (size_t)rb * DD + col) = v;
            }
        }
    }
}

// fused: blocks [0, GRIDG) run gemm1 (x@W1 -> scaled bufA);
//        blocks [GRIDG, GRIDG+GRIDE) run the independent CSR fill.
__global__ void __launch_bounds__(256) k_fill_gemm1(const int* __restrict__ src,
                                                    const int* __restrict__ dst,
                                                    const float* __restrict__ X,
                                                    const float* __restrict__ W) {
    __shared__ float sX[64 * SXS];
    __shared__ float sW[32 * SWS];
    if (blockIdx.x < GRIDG) {
        gemm_core(blockIdx.x, X, W, g_bufA, NN, sX, sW);
    } else {
        int e = (blockIdx.x - GRIDG) * 256 + threadIdx.x;
        if (e < EE) {
            int d = dst[e];
            int pos = atomicAdd(&g_cursor[d], 1);
            g_csrc[pos] = src[e];
        }
    }
}

__global__ void __launch_bounds__(256) k_gemm2(const float* __restrict__ W) {
    __shared__ float sX[64 * SXS];
    __shared__ float sW[32 * SWS];
    gemm_core(blockIdx.x, g_bufB, W, g_bufA, NN, sX, sW);
}

// ================= aggregation: warp per node, ILP-4 gathers, no atomics ======
// bufA holds Hs = (XW)*dinv.  res = dinv[i] * ( Hs[i] + sum_{s->i} Hs[s] )
__device__ __forceinline__ float4 agg_node(int i, int lane) {
    const float4* H4 = (const float4*)g_bufA;
    float di = g_dinv[i];

    float4 acc = H4[(size_t)i * 32 + lane];   // self term (pre-scaled)
    int j  = g_rows[i];
    int en = j + g_dege[i];
    for (; j + 4 <= en; j += 4) {
        int s0 = __ldg(&g_csrc[j]);
        int s1 = __ldg(&g_csrc[j + 1]);
        int s2 = __ldg(&g_csrc[j + 2]);
        int s3 = __ldg(&g_csrc[j + 3]);
        float4 v0 = H4[(size_t)s0 * 32 + lane];
        float4 v1 = H4[(size_t)s1 * 32 + lane];
        float4 v2 = H4[(size_t)s2 * 32 + lane];
        float4 v3 = H4[(size_t)s3 * 32 + lane];
        acc.x += v0.x + v1.x + v2.x + v3.x;
        acc.y += v0.y + v1.y + v2.y + v3.y;
        acc.z += v0.z + v1.z + v2.z + v3.z;
        acc.w += v0.w + v1.w + v2.w + v3.w;
    }
    for (; j < en; j++) {
        int s = __ldg(&g_csrc[j]);
        float4 v = H4[(size_t)s * 32 + lane];
        acc.x += v.x; acc.y += v.y; acc.z += v.z; acc.w += v.w;
    }
    acc.x *= di; acc.y *= di; acc.z *= di; acc.w *= di;
    return acc;
}

// layer-1 epilogue: relu(acc + b1) -> g_bufB
__global__ void k_agg_relu(const float* __restrict__ b) {
    int gid  = blockIdx.x * blockDim.x + threadIdx.x;
    int i    = gid >> 5;
    if (i >= NN) return;
    int lane = gid & 31;

    float4 acc = agg_node(i, lane);
    float4 bb = ((const float4*)b)[lane];
    acc.x = fmaxf(acc.x + bb.x, 0.f);
    acc.y = fmaxf(acc.y + bb.y, 0.f);
    acc.z = fmaxf(acc.z + bb.z, 0.f);
    acc.w = fmaxf(acc.w + bb.w, 0.f);
    ((float4*)(g_bufB + (size_t)i * DD))[lane] = acc;
}

// layer-2 epilogue: relu(acc + b2), then two head dot-products -> out
__global__ void k_agg_heads(const float* __restrict__ b2,
                            const float* __restrict__ Wt, const float* __restrict__ bt,
                            const float* __restrict__ We, const float* __restrict__ be,
                            float* __restrict__ out) {
    int gid  = blockIdx.x * blockDim.x + threadIdx.x;
    int i    = gid >> 5;
    if (i >= NN) return;
    int lane = gid & 31;

    float4 acc = agg_node(i, lane);
    float4 bb = ((const float4*)b2)[lane];
    acc.x = fmaxf(acc.x + bb.x, 0.f);
    acc.y = fmaxf(acc.y + bb.y, 0.f);
    acc.z = fmaxf(acc.z + bb.z, 0.f);
    acc.w = fmaxf(acc.w + bb.w, 0.f);

    float4 wt = ((const float4*)Wt)[lane];
    float4 we = ((const float4*)We)[lane];
    float stv = acc.x * wt.x + acc.y * wt.y + acc.z * wt.z + acc.w * wt.w;
    float evv = acc.x * we.x + acc.y * we.y + acc.z * we.z + acc.w * we.w;
#pragma unroll
    for (int off = 16; off > 0; off >>= 1) {
        stv += __shfl_xor_sync(0xFFFFFFFF, stv, off);
        evv += __shfl_xor_sync(0xFFFFFFFF, evv, off);
    }
    if (lane == 0) {
        out[i]      = stv + bt[0];
        out[NN + i] = evv + be[0];
    }
}

// ================= launch =================
extern "C" void kernel_launch(void* const* d_in, const int* in_sizes, int n_in,
                              void* d_out, int out_size) {
    const float* x  = (const float*)d_in[0];
    const int*   ei = (const int*)  d_in[1];
    const float* W1 = (const float*)d_in[2];
    const float* b1 = (const float*)d_in[3];
    const float* W2 = (const float*)d_in[4];
    const float* b2 = (const float*)d_in[5];
    const float* Wt = (const float*)d_in[6];
    const float* bt = (const float*)d_in[7];
    const float* We = (const float*)d_in[8];
    const float* be = (const float*)d_in[9];
    float* out = (float*)d_out;

    const int* src = ei;        // edge_index[0]
    const int* dst = ei + EE;   // edge_index[1]

    const int T = 256;
    int gridN   = (NN + T - 1) / T;      // 196
    int gridE   = (EE + T - 1) / T;      // 3125
    int gridN32 = (NN * 32 + T - 1) / T; // 6250

    // CSR build + normalization
    k_zero  <<<gridN, T>>>();
    k_count <<<gridE, T>>>(dst);
    k_scanA <<<NBLK, 256>>>();
    k_scanC <<<NBLK, 256>>>();

    // layer 1: CSR fill runs concurrently with gemm1 inside one kernel
    k_fill_gemm1<<<GRIDG + GRIDE, T>>>(src, dst, x, W1);
    k_agg_relu  <<<gridN32, T>>>(b1);

    // layer 2
    k_gemm2     <<<GRIDG, T>>>(W2);
    k_agg_heads <<<gridN32, T>>>(b2, Wt, bt, We, be, out);
}